// round 1
// baseline (speedup 1.0000x reference)
#include <cuda_runtime.h>
#include <cstdint>
#include <cstddef>

#define NTHREADS 256
#define D 1024
#define D4 (D / 4)
#define NS 25
#define NWAY 5
#define SROWS 28          // 25 rows padded to 28 (7 blocks of 4) with zero rows
#define SPITCH 1028       // 1024 + 4 floats: kills bank conflicts, keeps 16B align
#define AUGC 32           // augmented matrix row stride (25 K cols + 5 Y + pad)
#define NCOLS 30          // active columns in augmented matrix

struct SmemLayout {
    float S[SROWS * SPITCH];   // 115136 B
    float M[NS * AUGC];        //   3200 B  augmented [K | Y] -> [I | A]
    float f[32];               //    128 B  pivot-column factors
    float Wt[NWAY * D];        //  20480 B  W transposed: Wt[c][k]
};                             // total ~138944 B

__global__ void __launch_bounds__(NTHREADS, 1)
ridge_head_kernel(const float* __restrict__ query,
                  const float* __restrict__ support,
                  const void* __restrict__ labels_raw,
                  const float* __restrict__ scale,
                  float* __restrict__ out,
                  int NQ)
{
    extern __shared__ __align__(16) char smem_raw[];
    SmemLayout* sm = reinterpret_cast<SmemLayout*>(smem_raw);

    const int b    = blockIdx.x;
    const int tid  = threadIdx.x;
    const int lane = tid & 31;
    const int warp = tid >> 5;

    // ---- label dtype detection (int64 vs int32), from block 0's region ----
    // If int64 (little-endian) the high 32-bit words of the first 25 entries
    // are all zero (labels are 0..4). Probability of false positive for an
    // int32 buffer: (1/5)^25. Reads stay within the first 200 bytes of the
    // buffer, in-bounds under either interpretation.
    const int* li = reinterpret_cast<const int*>(labels_raw);
    bool is64 = true;
    #pragma unroll
    for (int i = 0; i < NS; i++)
        if (li[2 * i + 1] != 0) is64 = false;

    // ---------------- Phase 1: load S tile + one-hot Y ----------------
    const float* Sg = support + (size_t)b * NS * D;
    for (int idx = tid; idx < SROWS * D4; idx += NTHREADS) {
        int row = idx / D4;
        int k4  = idx - row * D4;
        float4 v = make_float4(0.f, 0.f, 0.f, 0.f);
        if (row < NS)
            v = reinterpret_cast<const float4*>(Sg)[row * D4 + k4];
        float* dst = &sm->S[row * SPITCH + k4 * 4];
        dst[0] = v.x; dst[1] = v.y; dst[2] = v.z; dst[3] = v.w;
    }
    if (tid < NS * NWAY) {
        int i = tid / NWAY;
        int c = tid - i * NWAY;
        long long lbl;
        if (is64)
            lbl = reinterpret_cast<const long long*>(labels_raw)[(size_t)b * NS + i];
        else
            lbl = (long long)reinterpret_cast<const int*>(labels_raw)[(size_t)b * NS + i];
        sm->M[i * AUGC + NS + c] = (lbl == (long long)c) ? 1.0f : 0.0f;
    }
    __syncthreads();

    // ---------------- Phase 2: K = S S^T + I (warp 4x4 register tiles) ----
    // 7 row-blocks of 4 -> 28 upper-triangle block pairs, round-robin on warps.
    for (int t = warp; t < 28; t += 8) {
        int tt = t, bi = 0;
        while (tt >= 7 - bi) { tt -= 7 - bi; bi++; }
        int bj = bi + tt;

        float acc[4][4];
        #pragma unroll
        for (int r = 0; r < 4; r++)
            #pragma unroll
            for (int s = 0; s < 4; s++) acc[r][s] = 0.f;

        #pragma unroll
        for (int it = 0; it < 8; it++) {
            int k = (lane + 32 * it) * 4;
            float4 a[4], bb[4];
            #pragma unroll
            for (int r = 0; r < 4; r++)
                a[r] = *reinterpret_cast<const float4*>(&sm->S[(bi * 4 + r) * SPITCH + k]);
            #pragma unroll
            for (int s = 0; s < 4; s++)
                bb[s] = *reinterpret_cast<const float4*>(&sm->S[(bj * 4 + s) * SPITCH + k]);
            #pragma unroll
            for (int r = 0; r < 4; r++)
                #pragma unroll
                for (int s = 0; s < 4; s++)
                    acc[r][s] += a[r].x * bb[s].x + a[r].y * bb[s].y +
                                 a[r].z * bb[s].z + a[r].w * bb[s].w;
        }
        #pragma unroll
        for (int r = 0; r < 4; r++)
            #pragma unroll
            for (int s = 0; s < 4; s++) {
                float v = acc[r][s];
                #pragma unroll
                for (int o = 16; o > 0; o >>= 1)
                    v += __shfl_xor_sync(0xffffffffu, v, o);
                if (lane == 0) {
                    int i = bi * 4 + r, j = bj * 4 + s;
                    if (i < NS && j < NS) {
                        float kv = v + (i == j ? 1.0f : 0.0f);  // + lambda*I
                        sm->M[i * AUGC + j] = kv;
                        sm->M[j * AUGC + i] = kv;
                    }
                }
            }
    }
    __syncthreads();

    // ---------------- Phase 3: Gauss-Jordan on [K | Y] (SPD, no pivoting) --
    for (int p = 0; p < NS; p++) {
        float inv = 1.0f / sm->M[p * AUGC + p];   // all threads read (broadcast)
        __syncthreads();                          // reads done before row-p writes
        if (tid < NCOLS) {
            sm->M[p * AUGC + tid] *= inv;         // scale pivot row
        } else if (tid >= 32 && tid < 32 + NS) {
            sm->f[tid - 32] = sm->M[(tid - 32) * AUGC + p];  // pivot column
        }
        __syncthreads();
        for (int s = tid; s < NS * NCOLS; s += NTHREADS) {
            int i = s / NCOLS;
            int j = s - i * NCOLS;
            if (i != p)
                sm->M[i * AUGC + j] -= sm->f[i] * sm->M[p * AUGC + j];
        }
        __syncthreads();
    }
    // A[i][c] now lives at M[i][25 + c]

    // ---------------- Phase 4: Wt[c][k] = sum_i S[i][k] * A[i][c] ----------
    for (int k = tid; k < D; k += NTHREADS) {
        float acc[NWAY] = {0.f, 0.f, 0.f, 0.f, 0.f};
        #pragma unroll
        for (int i = 0; i < NS; i++) {
            float s = sm->S[i * SPITCH + k];
            #pragma unroll
            for (int c = 0; c < NWAY; c++)
                acc[c] += s * sm->M[i * AUGC + NS + c];
        }
        #pragma unroll
        for (int c = 0; c < NWAY; c++)
            sm->Wt[c * D + k] = acc[c];
    }
    __syncthreads();

    // ---------------- Phase 5: logits = scale * (Q @ W), stream Q once -----
    const float* Qg = query + (size_t)b * NQ * D;
    float* Ob = out + (size_t)b * NQ * NWAY;
    const float scl = __ldg(scale);
    const int ngroups = (NQ + 3) >> 2;

    for (int g = warp; g < ngroups; g += 8) {
        const int r0 = g * 4;
        float acc[4][NWAY];
        #pragma unroll
        for (int r = 0; r < 4; r++)
            #pragma unroll
            for (int c = 0; c < NWAY; c++) acc[r][c] = 0.f;

        #pragma unroll
        for (int it = 0; it < 8; it++) {
            const int k = (lane + 32 * it) * 4;
            float4 w[NWAY];
            #pragma unroll
            for (int c = 0; c < NWAY; c++)
                w[c] = *reinterpret_cast<const float4*>(&sm->Wt[c * D + k]);
            #pragma unroll
            for (int r = 0; r < 4; r++) {
                const int rr = r0 + r;
                if (rr < NQ) {
                    float4 q = *reinterpret_cast<const float4*>(&Qg[(size_t)rr * D + k]);
                    #pragma unroll
                    for (int c = 0; c < NWAY; c++)
                        acc[r][c] += q.x * w[c].x + q.y * w[c].y +
                                     q.z * w[c].z + q.w * w[c].w;
                }
            }
        }
        #pragma unroll
        for (int r = 0; r < 4; r++)
            #pragma unroll
            for (int c = 0; c < NWAY; c++) {
                float v = acc[r][c];
                #pragma unroll
                for (int o = 16; o > 0; o >>= 1)
                    v += __shfl_xor_sync(0xffffffffu, v, o);
                if (lane == 0 && (r0 + r) < NQ)
                    Ob[(size_t)(r0 + r) * NWAY + c] = scl * v;
            }
    }
}

extern "C" void kernel_launch(void* const* d_in, const int* in_sizes, int n_in,
                              void* d_out, int out_size)
{
    const float* query   = (const float*)d_in[0];
    const float* support = (const float*)d_in[1];
    const void*  labels  = d_in[2];
    const float* scale   = (const float*)d_in[3];

    const int B  = in_sizes[1] / (NS * D);
    const int NQ = in_sizes[0] / (B * D);

    // Idempotent, called every time (no static guards). Not a stream op, so
    // it is legal during graph capture.
    cudaFuncSetAttribute(ridge_head_kernel,
                         cudaFuncAttributeMaxDynamicSharedMemorySize,
                         (int)sizeof(SmemLayout));

    ridge_head_kernel<<<B, NTHREADS, sizeof(SmemLayout)>>>(
        query, support, labels, scale, (float*)d_out, NQ);
}

// round 3
// speedup vs baseline: 1.3561x; 1.3561x over previous
#include <cuda_runtime.h>
#include <cstdint>
#include <cstddef>

#define NTHREADS 256
#define D        1024
#define NS       25
#define NWAY     5
#define SROWS    28        // 25 rows padded to 28 (7 blocks of 4)
#define CW       256       // S chunk width (floats)
#define CP       260       // chunk pitch
#define NCHUNK   (D / CW)  // 4
#define AUGC     32        // augmented matrix row stride
#define NCOLS    30        // active augmented columns
#define QSPLIT   3

// scratch: W^T per batch, class-major: g_Wt[b*5120 + c*1024 + k]
__device__ float g_Wt[1024 * NWAY * D];

// ---------------------------------------------------------------------------
// Kernel A: per-batch ridge solve -> W^T into g_Wt
// ---------------------------------------------------------------------------
struct SmA {
    float Sc[SROWS * CP];   // 29120 B  S chunk
    float M[NS * AUGC];     //  3200 B  augmented [K | Y] -> [I | A]
    float f[32];            //   128 B  pivot column
};

__global__ void __launch_bounds__(NTHREADS, 3)
solve_w_kernel(const float* __restrict__ support,
               const void* __restrict__ labels_raw,
               float* __restrict__ wt_out)
{
    extern __shared__ __align__(16) char smem_raw[];
    SmA* sm = reinterpret_cast<SmA*>(smem_raw);

    const int b    = blockIdx.x;
    const int tid  = threadIdx.x;
    const int lane = tid & 31;
    const int warp = tid >> 5;

    // label dtype detection (int64 vs int32): high words of first 25 entries
    const int* li = reinterpret_cast<const int*>(labels_raw);
    bool is64 = true;
    #pragma unroll
    for (int i = 0; i < NS; i++)
        if (li[2 * i + 1] != 0) is64 = false;

    // ---- Phase 0: init augmented matrix M = [lambda*I | one_hot(Y)] ------
    for (int s = tid; s < NS * AUGC; s += NTHREADS) {
        int i = s / AUGC, j = s - i * AUGC;
        float v;
        if (j < NS) {
            v = (i == j) ? 1.0f : 0.0f;     // K starts at lambda*I, SS^T added below
        } else if (j < NS + NWAY) {
            int c = j - NS;
            long long lbl;
            if (is64)
                lbl = reinterpret_cast<const long long*>(labels_raw)[(size_t)b * NS + i];
            else
                lbl = (long long)li[(size_t)b * NS + i];
            v = (lbl == (long long)c) ? 1.0f : 0.0f;
        } else {
            v = 0.0f;
        }
        sm->M[s] = v;
    }

    // ---- Phase 1+2: K += S S^T, chunked over D --------------------------
    const float4* Sg4 = reinterpret_cast<const float4*>(support + (size_t)b * NS * D);
    for (int ch = 0; ch < NCHUNK; ch++) {
        // load 28 x 256 chunk (rows 25..27 zero)
        for (int idx = tid; idx < SROWS * (CW / 4); idx += NTHREADS) {
            int row = idx / (CW / 4);
            int k4  = idx - row * (CW / 4);
            float4 v = make_float4(0.f, 0.f, 0.f, 0.f);
            if (row < NS)
                v = Sg4[row * (D / 4) + ch * (CW / 4) + k4];
            float* dst = &sm->Sc[row * CP + k4 * 4];
            dst[0] = v.x; dst[1] = v.y; dst[2] = v.z; dst[3] = v.w;
        }
        __syncthreads();

        // 28 upper-triangle 4x4 block tiles over 8 warps
        for (int pass = 0; pass < 4; pass++) {
            int t = warp + 8 * pass;
            if (t >= 28) break;
            int tt = t, bi = 0;
            while (tt >= 7 - bi) { tt -= 7 - bi; bi++; }
            int bj = bi + tt;

            float acc[4][4];
            #pragma unroll
            for (int r = 0; r < 4; r++)
                #pragma unroll
                for (int s = 0; s < 4; s++) acc[r][s] = 0.f;

            #pragma unroll
            for (int it = 0; it < CW / 128; it++) {   // 2 iters
                int k = (lane + 32 * it) * 4;
                float4 a[4], bb[4];
                #pragma unroll
                for (int r = 0; r < 4; r++)
                    a[r] = *reinterpret_cast<const float4*>(&sm->Sc[(bi * 4 + r) * CP + k]);
                #pragma unroll
                for (int s = 0; s < 4; s++)
                    bb[s] = *reinterpret_cast<const float4*>(&sm->Sc[(bj * 4 + s) * CP + k]);
                #pragma unroll
                for (int r = 0; r < 4; r++)
                    #pragma unroll
                    for (int s = 0; s < 4; s++)
                        acc[r][s] += a[r].x * bb[s].x + a[r].y * bb[s].y +
                                     a[r].z * bb[s].z + a[r].w * bb[s].w;
            }
            #pragma unroll
            for (int r = 0; r < 4; r++)
                #pragma unroll
                for (int s = 0; s < 4; s++) {
                    float v = acc[r][s];
                    #pragma unroll
                    for (int o = 16; o > 0; o >>= 1)
                        v += __shfl_xor_sync(0xffffffffu, v, o);
                    if (lane == 0) {
                        int i = bi * 4 + r, j = bj * 4 + s;
                        if (i < NS && j < NS) {
                            if (bi != bj) {
                                // off-diagonal block: each (i,j) pair appears
                                // in exactly one tile element
                                sm->M[i * AUGC + j] += v;
                                sm->M[j * AUGC + i] += v;
                            } else if (r == s) {
                                sm->M[i * AUGC + i] += v;
                            } else if (s > r) {
                                // diagonal block: emit each symmetric pair once
                                sm->M[i * AUGC + j] += v;
                                sm->M[j * AUGC + i] += v;
                            }
                            // s < r in diagonal block: skip (duplicate of s > r)
                        }
                    }
                }
        }
        __syncthreads();
    }

    // ---- Phase 3: Gauss-Jordan on [K | Y] (SPD, no pivoting) -------------
    for (int p = 0; p < NS; p++) {
        float inv = 1.0f / sm->M[p * AUGC + p];
        __syncthreads();
        if (tid < NCOLS) {
            sm->M[p * AUGC + tid] *= inv;
        } else if (tid >= 32 && tid < 32 + NS) {
            sm->f[tid - 32] = sm->M[(tid - 32) * AUGC + p];
        }
        __syncthreads();
        for (int s = tid; s < NS * NCOLS; s += NTHREADS) {
            int i = s / NCOLS;
            int j = s - i * NCOLS;
            if (i != p)
                sm->M[i * AUGC + j] -= sm->f[i] * sm->M[p * AUGC + j];
        }
        __syncthreads();
    }
    // A[i][c] at M[i][25 + c]

    // ---- Phase 4: Wt[c][k] = sum_i S[i][k] * A[i][c], S from global (L2) --
    {
        float4 acc[NWAY];
        #pragma unroll
        for (int c = 0; c < NWAY; c++) acc[c] = make_float4(0.f, 0.f, 0.f, 0.f);
        #pragma unroll
        for (int i = 0; i < NS; i++) {
            float4 s = Sg4[i * (D / 4) + tid];
            #pragma unroll
            for (int c = 0; c < NWAY; c++) {
                float a = sm->M[i * AUGC + NS + c];
                acc[c].x += s.x * a; acc[c].y += s.y * a;
                acc[c].z += s.z * a; acc[c].w += s.w * a;
            }
        }
        float4* Wt4 = reinterpret_cast<float4*>(wt_out + (size_t)b * NWAY * D);
        #pragma unroll
        for (int c = 0; c < NWAY; c++)
            Wt4[c * (D / 4) + tid] = acc[c];
    }
}

// ---------------------------------------------------------------------------
// Kernel B: logits = scale * Q @ W, grid (QSPLIT, B)
// ---------------------------------------------------------------------------
struct SmB {
    float Wt[NWAY * D];     // 20480 B, class-major
};

__global__ void __launch_bounds__(NTHREADS, 4)
logits_kernel(const float* __restrict__ query,
              const float* __restrict__ wt_in,
              const float* __restrict__ scale,
              float* __restrict__ out,
              int NQ, int rows_per_sub)
{
    extern __shared__ __align__(16) char smem_raw[];
    SmB* sm = reinterpret_cast<SmB*>(smem_raw);

    const int b    = blockIdx.y;
    const int sub  = blockIdx.x;
    const int tid  = threadIdx.x;
    const int lane = tid & 31;
    const int warp = tid >> 5;

    // load W^T tile
    {
        const float4* src = reinterpret_cast<const float4*>(wt_in + (size_t)b * NWAY * D);
        float4* dst = reinterpret_cast<float4*>(sm->Wt);
        #pragma unroll
        for (int i = 0; i < (NWAY * D / 4 + NTHREADS - 1) / NTHREADS; i++) {
            int idx = tid + i * NTHREADS;
            if (idx < NWAY * D / 4) dst[idx] = src[idx];
        }
    }
    __syncthreads();

    const int row0 = sub * rows_per_sub;
    const int rows = min(rows_per_sub, NQ - row0);
    if (rows <= 0) return;

    const float* Qg = query + (size_t)b * NQ * D;
    float* Ob = out + (size_t)b * NQ * NWAY;
    const float scl = __ldg(scale);

    for (int g = warp; g * 4 < rows; g += 8) {
        const int r0 = g * 4;
        float acc[4][NWAY];
        #pragma unroll
        for (int r = 0; r < 4; r++)
            #pragma unroll
            for (int c = 0; c < NWAY; c++) acc[r][c] = 0.f;

        #pragma unroll
        for (int it = 0; it < 8; it++) {
            const int k = (lane + 32 * it) * 4;
            float4 w[NWAY];
            #pragma unroll
            for (int c = 0; c < NWAY; c++)
                w[c] = *reinterpret_cast<const float4*>(&sm->Wt[c * D + k]);
            #pragma unroll
            for (int r = 0; r < 4; r++) {
                if (r0 + r < rows) {
                    float4 q = *reinterpret_cast<const float4*>(
                        &Qg[(size_t)(row0 + r0 + r) * D + k]);
                    #pragma unroll
                    for (int c = 0; c < NWAY; c++)
                        acc[r][c] += q.x * w[c].x + q.y * w[c].y +
                                     q.z * w[c].z + q.w * w[c].w;
                }
            }
        }
        #pragma unroll
        for (int r = 0; r < 4; r++)
            #pragma unroll
            for (int c = 0; c < NWAY; c++) {
                float v = acc[r][c];
                #pragma unroll
                for (int o = 16; o > 0; o >>= 1)
                    v += __shfl_xor_sync(0xffffffffu, v, o);
                if (lane == 0 && r0 + r < rows)
                    Ob[(size_t)(row0 + r0 + r) * NWAY + c] = scl * v;
            }
    }
}

extern "C" void kernel_launch(void* const* d_in, const int* in_sizes, int n_in,
                              void* d_out, int out_size)
{
    const float* query   = (const float*)d_in[0];
    const float* support = (const float*)d_in[1];
    const void*  labels  = d_in[2];
    const float* scale   = (const float*)d_in[3];

    const int B  = in_sizes[1] / (NS * D);
    const int NQ = in_sizes[0] / (B * D);
    const int rows_per_sub = (NQ + QSPLIT - 1) / QSPLIT;

    float* wt;
    cudaGetSymbolAddress((void**)&wt, g_Wt);

    cudaFuncSetAttribute(solve_w_kernel,
                         cudaFuncAttributeMaxDynamicSharedMemorySize, (int)sizeof(SmA));
    cudaFuncSetAttribute(logits_kernel,
                         cudaFuncAttributeMaxDynamicSharedMemorySize, (int)sizeof(SmB));

    solve_w_kernel<<<B, NTHREADS, sizeof(SmA)>>>(support, labels, wt);

    dim3 gridB(QSPLIT, B);
    logits_kernel<<<gridB, NTHREADS, sizeof(SmB)>>>(query, wt, scale,
                                                    (float*)d_out, NQ, rows_per_sub);
}

// round 4
// speedup vs baseline: 2.0203x; 1.4898x over previous
#include <cuda_runtime.h>
#include <cstdint>
#include <cstddef>

#define D        1024
#define D4       256
#define NS       25
#define NWAY     5
#define NCHUNK   4
#define CW       256       // chunk width (floats)
#define CW4      64
#define CP       260       // chunk pitch (floats)
#define SROWS    28        // 25 rows padded to 28 (7 blocks of 4)
#define AUGC     32        // augmented matrix row stride
#define NCOLS    30        // active augmented columns
#define MAXB     1024
#define ROWS_PER_CTA 16    // 8 warps x 2 rows

// global scratch
__device__ float g_Kp[MAXB * NCHUNK * NS * NS];  // partial K per chunk
__device__ float g_A [MAXB * NS * NWAY];         // K^{-1} Y
__device__ float g_Wt[MAXB * NWAY * D];          // W^T class-major

// ---------------------------------------------------------------------------
// Kernel 1: partial K = S_chunk S_chunk^T  -> g_Kp   grid(NCHUNK, B)
// ---------------------------------------------------------------------------
struct SmK { float Sc[SROWS * CP]; };             // 29120 B

__global__ void __launch_bounds__(256, 4)
kpart_kernel(const float* __restrict__ support, float* __restrict__ kp)
{
    extern __shared__ __align__(16) char smem_raw[];
    SmK* sm = reinterpret_cast<SmK*>(smem_raw);

    const int ch   = blockIdx.x;
    const int b    = blockIdx.y;
    const int tid  = threadIdx.x;
    const int lane = tid & 31;
    const int warp = tid >> 5;

    const float4* Sg4 = reinterpret_cast<const float4*>(support + (size_t)b * NS * D);

    // load 28 x 256 chunk (rows 25..27 zero)
    for (int idx = tid; idx < SROWS * CW4; idx += 256) {
        int row = idx / CW4;
        int k4  = idx - row * CW4;
        float4 v = make_float4(0.f, 0.f, 0.f, 0.f);
        if (row < NS)
            v = Sg4[row * D4 + ch * CW4 + k4];
        float* dst = &sm->Sc[row * CP + k4 * 4];
        dst[0] = v.x; dst[1] = v.y; dst[2] = v.z; dst[3] = v.w;
    }
    __syncthreads();

    float* outp = kp + ((size_t)b * NCHUNK + ch) * NS * NS;

    // 28 upper-triangle 4x4 block tiles over 8 warps
    for (int t = warp; t < 28; t += 8) {
        int tt = t, bi = 0;
        while (tt >= 7 - bi) { tt -= 7 - bi; bi++; }
        int bj = bi + tt;

        float acc[4][4];
        #pragma unroll
        for (int r = 0; r < 4; r++)
            #pragma unroll
            for (int s = 0; s < 4; s++) acc[r][s] = 0.f;

        #pragma unroll
        for (int it = 0; it < 2; it++) {
            int k = (lane + 32 * it) * 4;
            float4 a[4], bb[4];
            #pragma unroll
            for (int r = 0; r < 4; r++)
                a[r] = *reinterpret_cast<const float4*>(&sm->Sc[(bi * 4 + r) * CP + k]);
            #pragma unroll
            for (int s = 0; s < 4; s++)
                bb[s] = *reinterpret_cast<const float4*>(&sm->Sc[(bj * 4 + s) * CP + k]);
            #pragma unroll
            for (int r = 0; r < 4; r++)
                #pragma unroll
                for (int s = 0; s < 4; s++)
                    acc[r][s] += a[r].x * bb[s].x + a[r].y * bb[s].y +
                                 a[r].z * bb[s].z + a[r].w * bb[s].w;
        }
        #pragma unroll
        for (int r = 0; r < 4; r++)
            #pragma unroll
            for (int s = 0; s < 4; s++) {
                float v = acc[r][s];
                #pragma unroll
                for (int o = 16; o > 0; o >>= 1)
                    v += __shfl_xor_sync(0xffffffffu, v, o);
                if (lane == 0) {
                    int i = bi * 4 + r, j = bj * 4 + s;
                    if (i < NS && j < NS) {
                        // duplicate writes in diagonal blocks are bit-identical
                        outp[i * NS + j] = v;
                        outp[j * NS + i] = v;
                    }
                }
            }
    }
}

// ---------------------------------------------------------------------------
// Kernel 2: warp-synchronous Gauss-Jordan -> A = K^{-1} Y    grid(B), block 32
// ---------------------------------------------------------------------------
__global__ void __launch_bounds__(32, 16)
solve_kernel(const float* __restrict__ kp,
             const void* __restrict__ labels_raw,
             float* __restrict__ a_out)
{
    __shared__ float M[NS * AUGC];
    const int b    = blockIdx.x;
    const int lane = threadIdx.x;

    // sum 4 chunk partials + lambda*I
    const float* p0 = kp + (size_t)b * NCHUNK * NS * NS;
    for (int s = lane; s < NS * NS; s += 32) {
        int i = s / NS, j = s - i * NS;
        float v = p0[s] + p0[s + NS * NS] + p0[s + 2 * NS * NS] + p0[s + 3 * NS * NS];
        if (i == j) v += 1.0f;
        M[i * AUGC + j] = v;
    }
    // zero Y + pad columns
    for (int s = lane; s < NS * (AUGC - NS); s += 32) {
        int i = s / (AUGC - NS), j = s - i * (AUGC - NS);
        M[i * AUGC + NS + j] = 0.0f;
    }
    __syncwarp();

    // label dtype detection (int64 vs int32) via first 25 entries of buffer
    const int* li = reinterpret_cast<const int*>(labels_raw);
    int hi = (lane < NS) ? li[2 * lane + 1] : 0;
    unsigned nz = __ballot_sync(0xffffffffu, hi != 0);
    bool is64 = (nz == 0);

    if (lane < NS) {
        long long lbl;
        if (is64)
            lbl = reinterpret_cast<const long long*>(labels_raw)[(size_t)b * NS + lane];
        else
            lbl = (long long)li[(size_t)b * NS + lane];
        M[lane * AUGC + NS + (int)lbl] = 1.0f;
    }
    __syncwarp();

    // Gauss-Jordan, SPD, no pivoting, warp-synchronous
    for (int p = 0; p < NS; p++) {
        float inv = 1.0f / M[p * AUGC + p];
        float fr = (lane < NS) ? M[lane * AUGC + p] : 0.f;   // column p (pre-scale)
        __syncwarp();
        if (lane < NCOLS) M[p * AUGC + lane] *= inv;          // scale pivot row
        __syncwarp();
        #pragma unroll
        for (int it = 0; it < 24; it++) {                     // 24*32 >= 750
            int s = lane + it * 32;
            int i = s / NCOLS, j = s - i * NCOLS;
            bool act = (s < NS * NCOLS) && (i != p);
            float f = __shfl_sync(0xffffffffu, fr, act ? i : 0);
            float pv = M[p * AUGC + (act ? j : 0)];
            if (act) M[i * AUGC + j] -= f * pv;
        }
        __syncwarp();
    }

    // write A (25 x 5)
    for (int s = lane; s < NS * NWAY; s += 32) {
        int i = s / NWAY, c = s - i * NWAY;
        a_out[(size_t)b * NS * NWAY + s] = M[i * AUGC + NS + c];
    }
}

// ---------------------------------------------------------------------------
// Kernel 3: W^T[c][k] = sum_i S[i][k] A[i][c]     grid(B), block 256
// ---------------------------------------------------------------------------
__global__ void __launch_bounds__(256, 5)
wcomp_kernel(const float* __restrict__ support,
             const float* __restrict__ a_in,
             float* __restrict__ wt_out)
{
    __shared__ float A[NS * NWAY];
    const int b   = blockIdx.x;
    const int tid = threadIdx.x;

    if (tid < NS * NWAY) A[tid] = a_in[(size_t)b * NS * NWAY + tid];
    __syncthreads();

    const float4* Sg4 = reinterpret_cast<const float4*>(support + (size_t)b * NS * D);
    float4 acc[NWAY];
    #pragma unroll
    for (int c = 0; c < NWAY; c++) acc[c] = make_float4(0.f, 0.f, 0.f, 0.f);

    #pragma unroll
    for (int i = 0; i < NS; i++) {
        float4 s = __ldg(&Sg4[i * D4 + tid]);
        #pragma unroll
        for (int c = 0; c < NWAY; c++) {
            float a = A[i * NWAY + c];
            acc[c].x += s.x * a; acc[c].y += s.y * a;
            acc[c].z += s.z * a; acc[c].w += s.w * a;
        }
    }
    float4* Wt4 = reinterpret_cast<float4*>(wt_out + (size_t)b * NWAY * D);
    #pragma unroll
    for (int c = 0; c < NWAY; c++)
        Wt4[c * D4 + tid] = acc[c];
}

// ---------------------------------------------------------------------------
// Kernel 4: logits = scale * Q @ W      grid(ceil(NQ/16), B), block 256
// ---------------------------------------------------------------------------
struct SmB { float Wt[NWAY * D]; };   // 20480 B

__global__ void __launch_bounds__(256, 5)
logits_kernel(const float* __restrict__ query,
              const float* __restrict__ wt_in,
              const float* __restrict__ scale,
              float* __restrict__ out,
              int NQ)
{
    extern __shared__ __align__(16) char smem_raw[];
    SmB* sm = reinterpret_cast<SmB*>(smem_raw);

    const int b    = blockIdx.y;
    const int sub  = blockIdx.x;
    const int tid  = threadIdx.x;
    const int lane = tid & 31;
    const int warp = tid >> 5;

    // load W^T tile (1280 float4 / 256 threads = 5 each)
    {
        const float4* src = reinterpret_cast<const float4*>(wt_in + (size_t)b * NWAY * D);
        float4* dst = reinterpret_cast<float4*>(sm->Wt);
        #pragma unroll
        for (int i = 0; i < 5; i++)
            dst[tid + i * 256] = src[tid + i * 256];
    }
    __syncthreads();

    const int row0 = sub * ROWS_PER_CTA;
    const int rows = min(ROWS_PER_CTA, NQ - row0);
    if (rows <= 0) return;

    const int r0 = warp * 2;
    const bool v0 = r0 < rows;
    const bool v1 = r0 + 1 < rows;
    if (!v0) return;

    const float* Qg = query + ((size_t)b * NQ + row0) * D;
    const float4* q0 = reinterpret_cast<const float4*>(Qg + (size_t)r0 * D);
    const float4* q1 = reinterpret_cast<const float4*>(Qg + (size_t)(r0 + 1) * D);

    float acc0[NWAY] = {0.f, 0.f, 0.f, 0.f, 0.f};
    float acc1[NWAY] = {0.f, 0.f, 0.f, 0.f, 0.f};

    #pragma unroll
    for (int it = 0; it < 8; it++) {
        const int k4 = lane + 32 * it;
        float4 qa = q0[k4];
        float4 qb = v1 ? q1[k4] : make_float4(0.f, 0.f, 0.f, 0.f);
        #pragma unroll
        for (int c = 0; c < NWAY; c++) {
            float4 w = *reinterpret_cast<const float4*>(&sm->Wt[c * D + k4 * 4]);
            acc0[c] += qa.x * w.x + qa.y * w.y + qa.z * w.z + qa.w * w.w;
            acc1[c] += qb.x * w.x + qb.y * w.y + qb.z * w.z + qb.w * w.w;
        }
    }

    const float scl = __ldg(scale);
    float* Ob = out + ((size_t)b * NQ + row0 + r0) * NWAY;
    #pragma unroll
    for (int c = 0; c < NWAY; c++) {
        float x = acc0[c], y = acc1[c];
        #pragma unroll
        for (int o = 16; o > 0; o >>= 1) {
            x += __shfl_xor_sync(0xffffffffu, x, o);
            y += __shfl_xor_sync(0xffffffffu, y, o);
        }
        if (lane == 0) {
            Ob[c] = scl * x;
            if (v1) Ob[NWAY + c] = scl * y;
        }
    }
}

extern "C" void kernel_launch(void* const* d_in, const int* in_sizes, int n_in,
                              void* d_out, int out_size)
{
    const float* query   = (const float*)d_in[0];
    const float* support = (const float*)d_in[1];
    const void*  labels  = d_in[2];
    const float* scale   = (const float*)d_in[3];

    const int B  = in_sizes[1] / (NS * D);
    const int NQ = in_sizes[0] / (B * D);

    float *kp, *aa, *wt;
    cudaGetSymbolAddress((void**)&kp, g_Kp);
    cudaGetSymbolAddress((void**)&aa, g_A);
    cudaGetSymbolAddress((void**)&wt, g_Wt);

    cudaFuncSetAttribute(kpart_kernel,
                         cudaFuncAttributeMaxDynamicSharedMemorySize, (int)sizeof(SmK));
    cudaFuncSetAttribute(logits_kernel,
                         cudaFuncAttributeMaxDynamicSharedMemorySize, (int)sizeof(SmB));

    dim3 g1(NCHUNK, B);
    kpart_kernel<<<g1, 256, sizeof(SmK)>>>(support, kp);

    solve_kernel<<<B, 32>>>(kp, labels, aa);

    wcomp_kernel<<<B, 256>>>(support, aa, wt);

    dim3 g4((NQ + ROWS_PER_CTA - 1) / ROWS_PER_CTA, B);
    logits_kernel<<<g4, 256, sizeof(SmB)>>>(query, wt, scale, (float*)d_out, NQ);
}

// round 5
// speedup vs baseline: 2.0266x; 1.0031x over previous
#include <cuda_runtime.h>
#include <cstdint>
#include <cstddef>

#define D        1024
#define D4       256
#define NS       25
#define NWAY     5
#define NCHUNK   4
#define CW       256       // chunk width (floats)
#define CW4      64
#define CP       260       // chunk pitch (floats)
#define SROWS    28        // 25 rows padded to 28 (7 blocks of 4)
#define AUGC     32        // augmented matrix row stride
#define NCOLS    30        // active augmented columns
#define MAXB     1024
#define ROWS_PER_WARP 4
#define ROWS_PER_CTA  32   // 8 warps x 4 rows

// global scratch
__device__ float g_Kp[MAXB * NCHUNK * NS * NS];  // partial K per chunk
__device__ float g_Wt[MAXB * NWAY * D];          // W^T class-major

// ---------------------------------------------------------------------------
// Kernel 1: partial K = S_chunk S_chunk^T  -> g_Kp   grid(NCHUNK, B)
// ---------------------------------------------------------------------------
struct SmK { float Sc[SROWS * CP]; };             // 29120 B

__global__ void __launch_bounds__(256, 3)
kpart_kernel(const float* __restrict__ support, float* __restrict__ kp)
{
    extern __shared__ __align__(16) char smem_raw[];
    SmK* sm = reinterpret_cast<SmK*>(smem_raw);

    const int ch   = blockIdx.x;
    const int b    = blockIdx.y;
    const int tid  = threadIdx.x;
    const int lane = tid & 31;
    const int warp = tid >> 5;

    const float4* Sg4 = reinterpret_cast<const float4*>(support + (size_t)b * NS * D);

    // load 28 x 256 chunk (rows 25..27 zero)
    for (int idx = tid; idx < SROWS * CW4; idx += 256) {
        int row = idx / CW4;
        int k4  = idx - row * CW4;
        float4 v = make_float4(0.f, 0.f, 0.f, 0.f);
        if (row < NS)
            v = Sg4[row * D4 + ch * CW4 + k4];
        float* dst = &sm->Sc[row * CP + k4 * 4];
        dst[0] = v.x; dst[1] = v.y; dst[2] = v.z; dst[3] = v.w;
    }
    __syncthreads();

    float* outp = kp + ((size_t)b * NCHUNK + ch) * NS * NS;

    // 28 upper-triangle 4x4 block tiles over 8 warps
    for (int t = warp; t < 28; t += 8) {
        int tt = t, bi = 0;
        while (tt >= 7 - bi) { tt -= 7 - bi; bi++; }
        int bj = bi + tt;

        float acc[4][4];
        #pragma unroll
        for (int r = 0; r < 4; r++)
            #pragma unroll
            for (int s = 0; s < 4; s++) acc[r][s] = 0.f;

        #pragma unroll
        for (int it = 0; it < 2; it++) {
            int k = (lane + 32 * it) * 4;
            float4 a[4], bb[4];
            #pragma unroll
            for (int r = 0; r < 4; r++)
                a[r] = *reinterpret_cast<const float4*>(&sm->Sc[(bi * 4 + r) * CP + k]);
            #pragma unroll
            for (int s = 0; s < 4; s++)
                bb[s] = *reinterpret_cast<const float4*>(&sm->Sc[(bj * 4 + s) * CP + k]);
            #pragma unroll
            for (int r = 0; r < 4; r++)
                #pragma unroll
                for (int s = 0; s < 4; s++)
                    acc[r][s] += a[r].x * bb[s].x + a[r].y * bb[s].y +
                                 a[r].z * bb[s].z + a[r].w * bb[s].w;
        }
        #pragma unroll
        for (int r = 0; r < 4; r++)
            #pragma unroll
            for (int s = 0; s < 4; s++) {
                float v = acc[r][s];
                #pragma unroll
                for (int o = 16; o > 0; o >>= 1)
                    v += __shfl_xor_sync(0xffffffffu, v, o);
                if (lane == 0) {
                    int i = bi * 4 + r, j = bj * 4 + s;
                    if (i < NS && j < NS) {
                        // duplicate writes in diagonal blocks are bit-identical
                        outp[i * NS + j] = v;
                        outp[j * NS + i] = v;
                    }
                }
            }
    }
}

// ---------------------------------------------------------------------------
// Kernel 2: fused solve (warp 0, warp-synchronous GJ) + W = S^T A  grid(B)
// ---------------------------------------------------------------------------
__global__ void __launch_bounds__(256, 5)
solve_w_kernel(const float* __restrict__ kp,
               const void* __restrict__ labels_raw,
               const float* __restrict__ support,
               float* __restrict__ wt_out)
{
    __shared__ float M[NS * AUGC];
    const int b    = blockIdx.x;
    const int tid  = threadIdx.x;
    const int lane = tid & 31;
    const int warp = tid >> 5;

    // ---- reduce 4 chunk partials + lambda*I into smem (all threads) ------
    const float* p0 = kp + (size_t)b * NCHUNK * NS * NS;
    for (int s = tid; s < NS * NS; s += 256) {
        int i = s / NS, j = s - i * NS;
        float v = p0[s] + p0[s + NS * NS] + p0[s + 2 * NS * NS] + p0[s + 3 * NS * NS];
        if (i == j) v += 1.0f;
        M[i * AUGC + j] = v;
    }
    // zero Y + pad columns
    for (int s = tid; s < NS * (AUGC - NS); s += 256) {
        int i = s / (AUGC - NS), j = s - i * (AUGC - NS);
        M[i * AUGC + NS + j] = 0.0f;
    }
    __syncthreads();

    if (warp == 0) {
        // label dtype detection (int64 vs int32) via first 25 entries
        const int* li = reinterpret_cast<const int*>(labels_raw);
        int hi = (lane < NS) ? li[2 * lane + 1] : 0;
        unsigned nz = __ballot_sync(0xffffffffu, hi != 0);
        bool is64 = (nz == 0);

        if (lane < NS) {
            long long lbl;
            if (is64)
                lbl = reinterpret_cast<const long long*>(labels_raw)[(size_t)b * NS + lane];
            else
                lbl = (long long)li[(size_t)b * NS + lane];
            M[lane * AUGC + NS + (int)lbl] = 1.0f;
        }
        __syncwarp();

        // Gauss-Jordan, SPD, no pivoting, warp-synchronous
        for (int p = 0; p < NS; p++) {
            float inv = 1.0f / M[p * AUGC + p];
            float fr = (lane < NS) ? M[lane * AUGC + p] : 0.f;  // column p
            __syncwarp();
            if (lane < NCOLS) M[p * AUGC + lane] *= inv;         // scale pivot row
            __syncwarp();
            #pragma unroll
            for (int it = 0; it < 24; it++) {                    // 24*32 >= 750
                int s = lane + it * 32;
                int i = s / NCOLS, j = s - i * NCOLS;
                bool act = (s < NS * NCOLS) && (i != p);
                float f = __shfl_sync(0xffffffffu, fr, act ? i : 0);
                float pv = M[p * AUGC + (act ? j : 0)];
                if (act) M[i * AUGC + j] -= f * pv;
            }
            __syncwarp();
        }
    }
    __syncthreads();
    // A[i][c] at M[i][25 + c]

    // ---- W^T[c][k] = sum_i S[i][k] A[i][c]  (S from L2, all 256 threads) --
    const float4* Sg4 = reinterpret_cast<const float4*>(support + (size_t)b * NS * D);
    float4 acc[NWAY];
    #pragma unroll
    for (int c = 0; c < NWAY; c++) acc[c] = make_float4(0.f, 0.f, 0.f, 0.f);

    #pragma unroll
    for (int i = 0; i < NS; i++) {
        float4 s = __ldg(&Sg4[i * D4 + tid]);
        #pragma unroll
        for (int c = 0; c < NWAY; c++) {
            float a = M[i * AUGC + NS + c];
            acc[c].x += s.x * a; acc[c].y += s.y * a;
            acc[c].z += s.z * a; acc[c].w += s.w * a;
        }
    }
    float4* Wt4 = reinterpret_cast<float4*>(wt_out + (size_t)b * NWAY * D);
    #pragma unroll
    for (int c = 0; c < NWAY; c++)
        Wt4[c * D4 + tid] = acc[c];
}

// ---------------------------------------------------------------------------
// Kernel 3: logits = scale * Q @ W   grid(ceil(NQ/32), B), 4 rows/warp
// ---------------------------------------------------------------------------
struct SmB { float Wt[NWAY * D]; };   // 20480 B

__global__ void __launch_bounds__(256, 4)
logits_kernel(const float* __restrict__ query,
              const float* __restrict__ wt_in,
              const float* __restrict__ scale,
              float* __restrict__ out,
              int NQ)
{
    extern __shared__ __align__(16) char smem_raw[];
    SmB* sm = reinterpret_cast<SmB*>(smem_raw);

    const int b    = blockIdx.y;
    const int tid  = threadIdx.x;
    const int lane = tid & 31;
    const int warp = tid >> 5;

    // load W^T tile (1280 float4 / 256 threads = 5 each)
    {
        const float4* src = reinterpret_cast<const float4*>(wt_in + (size_t)b * NWAY * D);
        float4* dst = reinterpret_cast<float4*>(sm->Wt);
        #pragma unroll
        for (int i = 0; i < 5; i++)
            dst[tid + i * 256] = src[tid + i * 256];
    }
    __syncthreads();

    const int row0 = blockIdx.x * ROWS_PER_CTA;
    const int rows = min(ROWS_PER_CTA, NQ - row0);
    if (rows <= 0) return;

    const int r0 = warp * ROWS_PER_WARP;
    const int nr = min(ROWS_PER_WARP, rows - r0);
    if (nr <= 0) return;

    const float4* Q4 = reinterpret_cast<const float4*>(
        query + ((size_t)b * NQ + row0 + r0) * D);

    float acc[ROWS_PER_WARP][NWAY];
    #pragma unroll
    for (int r = 0; r < ROWS_PER_WARP; r++)
        #pragma unroll
        for (int c = 0; c < NWAY; c++) acc[r][c] = 0.f;

    #pragma unroll
    for (int it = 0; it < 8; it++) {
        const int k4 = lane + 32 * it;
        float4 q[ROWS_PER_WARP];
        #pragma unroll
        for (int r = 0; r < ROWS_PER_WARP; r++)
            q[r] = (r < nr) ? __ldcs(&Q4[(size_t)r * D4 + k4])
                            : make_float4(0.f, 0.f, 0.f, 0.f);
        #pragma unroll
        for (int c = 0; c < NWAY; c++) {
            float4 w = *reinterpret_cast<const float4*>(&sm->Wt[c * D + k4 * 4]);
            #pragma unroll
            for (int r = 0; r < ROWS_PER_WARP; r++)
                acc[r][c] += q[r].x * w.x + q[r].y * w.y +
                             q[r].z * w.z + q[r].w * w.w;
        }
    }

    const float scl = __ldg(scale);
    float* Ob = out + ((size_t)b * NQ + row0 + r0) * NWAY;
    #pragma unroll
    for (int r = 0; r < ROWS_PER_WARP; r++)
        #pragma unroll
        for (int c = 0; c < NWAY; c++) {
            float v = acc[r][c];
            #pragma unroll
            for (int o = 16; o > 0; o >>= 1)
                v += __shfl_xor_sync(0xffffffffu, v, o);
            if (lane == 0 && r < nr)
                Ob[(size_t)r * NWAY + c] = scl * v;
        }
}

extern "C" void kernel_launch(void* const* d_in, const int* in_sizes, int n_in,
                              void* d_out, int out_size)
{
    const float* query   = (const float*)d_in[0];
    const float* support = (const float*)d_in[1];
    const void*  labels  = d_in[2];
    const float* scale   = (const float*)d_in[3];

    const int B  = in_sizes[1] / (NS * D);
    const int NQ = in_sizes[0] / (B * D);

    float *kp, *wt;
    cudaGetSymbolAddress((void**)&kp, g_Kp);
    cudaGetSymbolAddress((void**)&wt, g_Wt);

    cudaFuncSetAttribute(kpart_kernel,
                         cudaFuncAttributeMaxDynamicSharedMemorySize, (int)sizeof(SmK));
    cudaFuncSetAttribute(logits_kernel,
                         cudaFuncAttributeMaxDynamicSharedMemorySize, (int)sizeof(SmB));

    dim3 g1(NCHUNK, B);
    kpart_kernel<<<g1, 256, sizeof(SmK)>>>(support, kp);

    solve_w_kernel<<<B, 256>>>(kp, labels, support, wt);

    dim3 g3((NQ + ROWS_PER_CTA - 1) / ROWS_PER_CTA, B);
    logits_kernel<<<g3, 256, sizeof(SmB)>>>(query, wt, scale, (float*)d_out, NQ);
}

// round 6
// speedup vs baseline: 2.0295x; 1.0014x over previous
#include <cuda_runtime.h>
#include <cstdint>
#include <cstddef>

#define D        1024
#define D4       256
#define NS       25
#define NWAY     5
#define NCHUNK   4
#define CW       256       // chunk width (floats)
#define CW4      64
#define CP       260       // chunk pitch (floats)
#define AUGC     32        // augmented matrix row stride
#define MAXB     1024
#define ROWS_PER_WARP 4
#define ROWS_PER_CTA  32   // 8 warps x 4 rows

// global scratch
__device__ float g_Kp[MAXB * NCHUNK * NS * NS];  // partial K per chunk
__device__ float g_A [MAXB * NS * NWAY];         // A = K^{-1} Y

// tile map: 15 upper-triangle pairs of 5 row-blocks
__constant__ unsigned char c_bi[15] = {0,0,0,0,0,1,1,1,1,2,2,2,3,3,4};
__constant__ unsigned char c_bj[15] = {0,1,2,3,4,1,2,3,4,2,3,4,3,4,4};

// ---------------------------------------------------------------------------
// Kernel 1: partial K = S_chunk S_chunk^T  -> g_Kp   grid(NCHUNK, B)
// ---------------------------------------------------------------------------
struct SmK { float Sc[NS * CP]; };                // 26000 B

__global__ void __launch_bounds__(256, 3)
kpart_kernel(const float* __restrict__ support, float* __restrict__ kp)
{
    extern __shared__ __align__(16) char smem_raw[];
    SmK* sm = reinterpret_cast<SmK*>(smem_raw);

    const int ch   = blockIdx.x;
    const int b    = blockIdx.y;
    const int tid  = threadIdx.x;
    const int lane = tid & 31;
    const int warp = tid >> 5;

    const float4* Sg4 = reinterpret_cast<const float4*>(support + (size_t)b * NS * D);

    // load 25 x 256 chunk (1600 float4)
    for (int idx = tid; idx < NS * CW4; idx += 256) {
        int row = idx / CW4;
        int k4  = idx - row * CW4;
        float4 v = Sg4[row * D4 + ch * CW4 + k4];
        float* dst = &sm->Sc[row * CP + k4 * 4];
        dst[0] = v.x; dst[1] = v.y; dst[2] = v.z; dst[3] = v.w;
    }
    __syncthreads();

    float* outp = kp + ((size_t)b * NCHUNK + ch) * NS * NS;

    // 15 upper-triangle 5x5 block tiles over 8 warps (2 rounds)
    for (int t = warp; t < 15; t += 8) {
        const int bi = c_bi[t] * 5;
        const int bj = c_bj[t] * 5;

        float acc[5][5];
        #pragma unroll
        for (int r = 0; r < 5; r++)
            #pragma unroll
            for (int s = 0; s < 5; s++) acc[r][s] = 0.f;

        #pragma unroll
        for (int it = 0; it < 2; it++) {
            const int k = (lane + 32 * it) * 4;
            float4 a[5];
            #pragma unroll
            for (int r = 0; r < 5; r++)
                a[r] = *reinterpret_cast<const float4*>(&sm->Sc[(bi + r) * CP + k]);
            #pragma unroll
            for (int s = 0; s < 5; s++) {
                float4 bv = *reinterpret_cast<const float4*>(&sm->Sc[(bj + s) * CP + k]);
                #pragma unroll
                for (int r = 0; r < 5; r++)
                    acc[r][s] += a[r].x * bv.x + a[r].y * bv.y +
                                 a[r].z * bv.z + a[r].w * bv.w;
            }
        }
        #pragma unroll
        for (int r = 0; r < 5; r++)
            #pragma unroll
            for (int s = 0; s < 5; s++) {
                float v = acc[r][s];
                #pragma unroll
                for (int o = 16; o > 0; o >>= 1)
                    v += __shfl_xor_sync(0xffffffffu, v, o);
                if (lane == 0) {
                    const int i = bi + r, j = bj + s;
                    // duplicate writes (diagonal tiles) are bit-identical
                    outp[i * NS + j] = v;
                    outp[j * NS + i] = v;
                }
            }
    }
}

// ---------------------------------------------------------------------------
// Kernel 2: warp-synchronous Gauss-Jordan, finalized-column skipping
//           A = (K + I)^{-1} Y       grid(B), block 32
// ---------------------------------------------------------------------------
__global__ void __launch_bounds__(32, 16)
solve_kernel(const float* __restrict__ kp,
             const void* __restrict__ labels_raw,
             float* __restrict__ a_out)
{
    __shared__ float M[NS * AUGC];
    const int b    = blockIdx.x;
    const int lane = threadIdx.x;

    // sum 4 chunk partials + lambda*I
    const float* p0 = kp + (size_t)b * NCHUNK * NS * NS;
    for (int s = lane; s < NS * NS; s += 32) {
        int i = s / NS, j = s - i * NS;
        float v = p0[s] + p0[s + NS * NS] + p0[s + 2 * NS * NS] + p0[s + 3 * NS * NS];
        if (i == j) v += 1.0f;
        M[i * AUGC + j] = v;
    }
    // zero Y + pad columns
    for (int s = lane; s < NS * (AUGC - NS); s += 32) {
        int i = s / (AUGC - NS), j = s - i * (AUGC - NS);
        M[i * AUGC + NS + j] = 0.0f;
    }
    __syncwarp();

    // label dtype detection (int64 vs int32) via first 25 entries
    const int* li = reinterpret_cast<const int*>(labels_raw);
    int hi = (lane < NS) ? li[2 * lane + 1] : 0;
    unsigned nz = __ballot_sync(0xffffffffu, hi != 0);
    bool is64 = (nz == 0);

    if (lane < NS) {
        long long lbl;
        if (is64)
            lbl = reinterpret_cast<const long long*>(labels_raw)[(size_t)b * NS + lane];
        else
            lbl = (long long)li[(size_t)b * NS + lane];
        M[lane * AUGC + NS + (int)lbl] = 1.0f;
    }
    __syncwarp();

    // Gauss-Jordan, SPD, no pivoting; columns j < p are already identity
    // (M[p][j] == 0 there), so only j in [p, 30) needs updating.
    for (int p = 0; p < NS; p++) {
        const float inv = 1.0f / M[p * AUGC + p];
        const float fr  = (lane < NS) ? M[lane * AUGC + p] : 0.f;  // column p
        __syncwarp();
        const int ncols = 30 - p;
        if (lane < ncols) M[p * AUGC + p + lane] *= inv;           // scale pivot row
        __syncwarp();
        const int total = NS * ncols;
        for (int base = 0; base < total; base += 32) {
            const int s = base + lane;
            int i = 0, j = 0;
            bool act = (s < total);
            if (act) { i = s / ncols; j = p + (s - i * ncols); }
            act = act && (i != p);
            float f  = __shfl_sync(0xffffffffu, fr, act ? i : 0);
            float pv = M[p * AUGC + (act ? j : p)];
            if (act) M[i * AUGC + j] -= f * pv;
        }
        __syncwarp();
    }

    // write A (25 x 5)
    for (int s = lane; s < NS * NWAY; s += 32) {
        int i = s / NWAY, c = s - i * NWAY;
        a_out[(size_t)b * NS * NWAY + s] = M[i * AUGC + NS + c];
    }
}

// ---------------------------------------------------------------------------
// Kernel 3: fused W = S^T A (into smem) + logits = scale * Q @ W
//           grid(ceil(NQ/32), B), block 256
// ---------------------------------------------------------------------------
struct SmF {
    float Wt[NWAY * D];      // 20480 B, class-major
    float A[NS * NWAY];      //   500 B
};

__global__ void __launch_bounds__(256, 4)
logits_kernel(const float* __restrict__ query,
              const float* __restrict__ support,
              const float* __restrict__ a_in,
              const float* __restrict__ scale,
              float* __restrict__ out,
              int NQ)
{
    extern __shared__ __align__(16) char smem_raw[];
    SmF* sm = reinterpret_cast<SmF*>(smem_raw);

    const int b    = blockIdx.y;
    const int tid  = threadIdx.x;
    const int lane = tid & 31;
    const int warp = tid >> 5;

    if (tid < NS * NWAY) sm->A[tid] = a_in[(size_t)b * NS * NWAY + tid];
    __syncthreads();

    // ---- W^T[c][k] = sum_i S[i][k] A[i][c]  (S from L2) -------------------
    {
        const float4* Sg4 = reinterpret_cast<const float4*>(support + (size_t)b * NS * D);
        float4 acc[NWAY];
        #pragma unroll
        for (int c = 0; c < NWAY; c++) acc[c] = make_float4(0.f, 0.f, 0.f, 0.f);
        #pragma unroll
        for (int i = 0; i < NS; i++) {
            float4 s = __ldg(&Sg4[i * D4 + tid]);
            #pragma unroll
            for (int c = 0; c < NWAY; c++) {
                float a = sm->A[i * NWAY + c];
                acc[c].x += s.x * a; acc[c].y += s.y * a;
                acc[c].z += s.z * a; acc[c].w += s.w * a;
            }
        }
        #pragma unroll
        for (int c = 0; c < NWAY; c++)
            *reinterpret_cast<float4*>(&sm->Wt[c * D + tid * 4]) = acc[c];
    }
    __syncthreads();

    // ---- logits, 4 rows per warp ------------------------------------------
    const int row0 = blockIdx.x * ROWS_PER_CTA;
    const int rows = min(ROWS_PER_CTA, NQ - row0);
    if (rows <= 0) return;

    const int r0 = warp * ROWS_PER_WARP;
    const int nr = min(ROWS_PER_WARP, rows - r0);
    if (nr <= 0) return;

    const float4* Q4 = reinterpret_cast<const float4*>(
        query + ((size_t)b * NQ + row0 + r0) * D);

    float acc[ROWS_PER_WARP][NWAY];
    #pragma unroll
    for (int r = 0; r < ROWS_PER_WARP; r++)
        #pragma unroll
        for (int c = 0; c < NWAY; c++) acc[r][c] = 0.f;

    #pragma unroll
    for (int it = 0; it < 8; it++) {
        const int k4 = lane + 32 * it;
        float4 q[ROWS_PER_WARP];
        #pragma unroll
        for (int r = 0; r < ROWS_PER_WARP; r++)
            q[r] = (r < nr) ? __ldcs(&Q4[(size_t)r * D4 + k4])
                            : make_float4(0.f, 0.f, 0.f, 0.f);
        #pragma unroll
        for (int c = 0; c < NWAY; c++) {
            float4 w = *reinterpret_cast<const float4*>(&sm->Wt[c * D + k4 * 4]);
            #pragma unroll
            for (int r = 0; r < ROWS_PER_WARP; r++)
                acc[r][c] += q[r].x * w.x + q[r].y * w.y +
                             q[r].z * w.z + q[r].w * w.w;
        }
    }

    const float scl = __ldg(scale);
    float* Ob = out + ((size_t)b * NQ + row0 + r0) * NWAY;
    #pragma unroll
    for (int r = 0; r < ROWS_PER_WARP; r++)
        #pragma unroll
        for (int c = 0; c < NWAY; c++) {
            float v = acc[r][c];
            #pragma unroll
            for (int o = 16; o > 0; o >>= 1)
                v += __shfl_xor_sync(0xffffffffu, v, o);
            if (lane == 0 && r < nr)
                Ob[(size_t)r * NWAY + c] = scl * v;
        }
}

extern "C" void kernel_launch(void* const* d_in, const int* in_sizes, int n_in,
                              void* d_out, int out_size)
{
    const float* query   = (const float*)d_in[0];
    const float* support = (const float*)d_in[1];
    const void*  labels  = d_in[2];
    const float* scale   = (const float*)d_in[3];

    const int B  = in_sizes[1] / (NS * D);
    const int NQ = in_sizes[0] / (B * D);

    float *kp, *aa;
    cudaGetSymbolAddress((void**)&kp, g_Kp);
    cudaGetSymbolAddress((void**)&aa, g_A);

    cudaFuncSetAttribute(kpart_kernel,
                         cudaFuncAttributeMaxDynamicSharedMemorySize, (int)sizeof(SmK));
    cudaFuncSetAttribute(logits_kernel,
                         cudaFuncAttributeMaxDynamicSharedMemorySize, (int)sizeof(SmF));

    dim3 g1(NCHUNK, B);
    kpart_kernel<<<g1, 256, sizeof(SmK)>>>(support, kp);

    solve_kernel<<<B, 32>>>(kp, labels, aa);

    dim3 g3((NQ + ROWS_PER_CTA - 1) / ROWS_PER_CTA, B);
    logits_kernel<<<g3, 256, sizeof(SmF)>>>(query, support, aa, scale,
                                            (float*)d_out, NQ);
}